// round 14
// baseline (speedup 1.0000x reference)
#include <cuda_runtime.h>
#include <cuda_fp16.h>
#include <cstdint>

// Problem constants (K_Rectify): B=128, NTOT=129, N=128, GS=16, C=384
#define PB    128
#define PNTOT 129
#define PN    128
#define PGS   16
#define PC    384
#define EPSW  0.05f
#define RMSE  1e-6f

#define NPTS (PB * PN)   // 16384

// fp16 staging of the gatherable point rows f[:,1:,:], row j = idx value.
// 16384 rows x 384 halves = 12.58 MB static __device__ scratch.
__device__ __align__(16) __half2 g_half[(size_t)NPTS * (PC / 2)];

static __device__ __forceinline__ __half2 u2h2(unsigned u) {
    __half2 h; *reinterpret_cast<unsigned*>(&h) = u; return h;
}
static __device__ __forceinline__ unsigned h22u(__half2 h) {
    return *reinterpret_cast<unsigned*>(&h);
}

// ---------------- Kernel 1: fp32 -> fp16 staging ----------------
__global__ void __launch_bounds__(256)
k_convert_kernel(const float* __restrict__ f)
{
    const int t  = blockIdx.x * blockDim.x + threadIdx.x;   // float4 slot
    const int r  = t / (PC / 4);                            // point row 0..16383
    const int c4 = t - r * (PC / 4);                        // float4 column 0..95

    const float4 v = reinterpret_cast<const float4*>(
        f + (size_t)((r >> 7) * PNTOT + 1 + (r & (PN - 1))) * PC)[c4];

    uint2 u;
    u.x = h22u(__floats2half2_rn(v.x, v.y));
    u.y = h22u(__floats2half2_rn(v.z, v.w));
    reinterpret_cast<uint2*>(g_half + (size_t)r * (PC / 2))[c4] = u;
}

// ---------------- Kernel 2: rectify ----------------
// 48 threads per point (8 channels each), 192-thread CTA = 4 points.
// Gathers: 16 x LDG.128 of fp16 per thread, accumulated with HFMA2 (2 banks).
// Blocks [0, NPTS/4): compute. Blocks [NPTS/4, NPTS/4+64): cls copy (2 batches each).
__global__ void __launch_bounds__(192, 8)
k_rectify_kernel(const float* __restrict__ f,
                 const float* __restrict__ dist,
                 const float* __restrict__ rf,
                 const float* __restrict__ knw,
                 const int* __restrict__ idx,
                 float* __restrict__ out)
{
    const int blk = blockIdx.x;
    const int tid = threadIdx.x;

    if (blk >= NPTS / 4) {
        // cls-token copy: 2 batches per block, 96 threads each
        const int b = (blk - NPTS / 4) * 2 + (tid >= 96 ? 1 : 0);
        const int t = tid - (tid >= 96 ? 96 : 0);
        const float4* src = reinterpret_cast<const float4*>(f  + (size_t)b * PNTOT * PC);
        float4*       dst = reinterpret_cast<float4*>(out + (size_t)b * PNTOT * PC);
        dst[t] = src[t];
        return;
    }

    const int q  = tid / 48;          // point within block, 0..3
    const int gt = tid - q * 48;      // group-local thread, 0..47
    const int p  = blk * 4 + q;       // global point

    __shared__ unsigned swh[4][PGS];  // half2-packed normalized weights
    __shared__ int      soff[4][PGS]; // gather row byte offsets into g_half
    __shared__ float    sred[4][3];   // RMS segment partials

    if (gt < PGS) {
        const float d = dist[p * PGS + gt];
        float wv = 1.0f / (d + EPSW);
        float s  = wv;
        const unsigned mask = 0xFFFFu << ((q & 1) * 16);  // the aligned 16-lane segment
        #pragma unroll
        for (int o = 8; o > 0; o >>= 1)
            s += __shfl_xor_sync(mask, s, o, 16);
        swh[q][gt]  = h22u(__float2half2_rn(wv / s));
        soff[q][gt] = idx[p * PGS + gt] * (PC * 2);       // row stride 768 bytes
    }
    __syncthreads();

    // x row (fp32, exact)
    const int b = p >> 7;
    const int n = p & (PN - 1);
    const int xoff = (b * PNTOT + 1 + n) * PC + gt * 8;
    const float4 x0 = *reinterpret_cast<const float4*>(f + (size_t)xoff);
    const float4 x1 = *reinterpret_cast<const float4*>(f + (size_t)xoff + 4);

    // Weighted gather: HFMA2 accumulation, two banks (even/odd g)
    const char* hb = reinterpret_cast<const char*>(g_half) + gt * 16;
    __half2 A0 = u2h2(0), A1 = u2h2(0), A2 = u2h2(0), A3 = u2h2(0);
    __half2 B0 = u2h2(0), B1 = u2h2(0), B2 = u2h2(0), B3 = u2h2(0);

    #pragma unroll
    for (int g = 0; g < PGS; g += 2) {
        const uint4 v0 = *reinterpret_cast<const uint4*>(hb + soff[q][g]);
        const __half2 w0 = u2h2(swh[q][g]);
        A0 = __hfma2(w0, u2h2(v0.x), A0);
        A1 = __hfma2(w0, u2h2(v0.y), A1);
        A2 = __hfma2(w0, u2h2(v0.z), A2);
        A3 = __hfma2(w0, u2h2(v0.w), A3);

        const uint4 v1 = *reinterpret_cast<const uint4*>(hb + soff[q][g + 1]);
        const __half2 w1 = u2h2(swh[q][g + 1]);
        B0 = __hfma2(w1, u2h2(v1.x), B0);
        B1 = __hfma2(w1, u2h2(v1.y), B1);
        B2 = __hfma2(w1, u2h2(v1.z), B2);
        B3 = __hfma2(w1, u2h2(v1.w), B3);
    }

    // Combine banks in fp32; sf = sum(w*nb) - x  (weights sum to 1)
    const float2 a0 = __half22float2(A0), b0f = __half22float2(B0);
    const float2 a1 = __half22float2(A1), b1f = __half22float2(B1);
    const float2 a2 = __half22float2(A2), b2f = __half22float2(B2);
    const float2 a3 = __half22float2(A3), b3f = __half22float2(B3);

    float s0 = a0.x + b0f.x - x0.x;
    float s1 = a0.y + b0f.y - x0.y;
    float s2 = a1.x + b1f.x - x0.z;
    float s3 = a1.y + b1f.y - x0.w;
    float s4 = a2.x + b2f.x - x1.x;
    float s5 = a2.y + b2f.y - x1.y;
    float s6 = a3.x + b3f.x - x1.z;
    float s7 = a3.y + b3f.y - x1.w;

    // RMS over the 384-channel row (48 threads x 8 ch)
    float ss = s0*s0 + s1*s1 + s2*s2 + s3*s3 + s4*s4 + s5*s5 + s6*s6 + s7*s7;
    #pragma unroll
    for (int o = 8; o > 0; o >>= 1)
        ss += __shfl_xor_sync(0xFFFFFFFFu, ss, o, 16);
    if ((gt & 15) == 0) sred[q][gt >> 4] = ss;   // seg 0..2
    __syncthreads();
    const float tot = sred[q][0] + sred[q][1] + sred[q][2];
    const float inv = rsqrtf(tot * (1.0f / PC) + RMSE);

    // out = rf[1+n] + x + (sf * inv) * knorm_w
    const float* rr = rf + (size_t)(1 + n) * PC + gt * 8;
    const float4 r0 = *reinterpret_cast<const float4*>(rr);
    const float4 r1 = *reinterpret_cast<const float4*>(rr + 4);
    const float4 k0 = *reinterpret_cast<const float4*>(knw + gt * 8);
    const float4 k1 = *reinterpret_cast<const float4*>(knw + gt * 8 + 4);

    float4 o4;
    o4.x = r0.x + x0.x + s0 * inv * k0.x;
    o4.y = r0.y + x0.y + s1 * inv * k0.y;
    o4.z = r0.z + x0.z + s2 * inv * k0.z;
    o4.w = r0.w + x0.w + s3 * inv * k0.w;
    *reinterpret_cast<float4*>(out + (size_t)xoff) = o4;

    o4.x = r1.x + x1.x + s4 * inv * k1.x;
    o4.y = r1.y + x1.y + s5 * inv * k1.y;
    o4.z = r1.z + x1.z + s6 * inv * k1.z;
    o4.w = r1.w + x1.w + s7 * inv * k1.w;
    *reinterpret_cast<float4*>(out + (size_t)xoff + 4) = o4;
}

extern "C" void kernel_launch(void* const* d_in, const int* in_sizes, int n_in,
                              void* d_out, int out_size)
{
    const float* f    = (const float*)d_in[0];
    const float* dist = (const float*)d_in[1];
    const float* rf   = (const float*)d_in[2];
    const float* knw  = (const float*)d_in[3];
    const int*   idx  = (const int*)d_in[4];
    float*       out  = (float*)d_out;

    const int conv_threads = NPTS * (PC / 4);              // 1,572,864
    k_convert_kernel<<<conv_threads / 256, 256>>>(f);

    const int grid = NPTS / 4 + PB / 2;                    // 4096 compute + 64 cls
    k_rectify_kernel<<<grid, 192>>>(f, dist, rf, knw, idx, out);
}

// round 15
// speedup vs baseline: 1.0799x; 1.0799x over previous
#include <cuda_runtime.h>
#include <cuda_fp16.h>
#include <cstdint>

// Problem constants (K_Rectify): B=128, NTOT=129, N=128, GS=16, C=384
#define PB    128
#define PNTOT 129
#define PN    128
#define PGS   16
#define PC    384
#define EPSW  0.05f
#define RMSE  1e-6f

#define NPTS (PB * PN)   // 16384

// fp16 staging of the gatherable point rows f[:,1:,:], row j = idx value.
// 16384 rows x 384 halves = 12.58 MB static __device__ scratch.
__device__ __align__(16) __half2 g_half[(size_t)NPTS * (PC / 2)];

static __device__ __forceinline__ __half2 u2h2(unsigned u) {
    __half2 h; *reinterpret_cast<unsigned*>(&h) = u; return h;
}
static __device__ __forceinline__ unsigned h22u(__half2 h) {
    return *reinterpret_cast<unsigned*>(&h);
}

// ---------------- Kernel 1: fp32 -> fp16 staging ----------------
__global__ void __launch_bounds__(256)
k_convert_kernel(const float* __restrict__ f)
{
    const int t  = blockIdx.x * blockDim.x + threadIdx.x;   // float4 slot
    const int r  = t / (PC / 4);                            // point row 0..16383
    const int c4 = t - r * (PC / 4);                        // float4 column 0..95

    const float4 v = reinterpret_cast<const float4*>(
        f + (size_t)((r >> 7) * PNTOT + 1 + (r & (PN - 1))) * PC)[c4];

    uint2 u;
    u.x = h22u(__floats2half2_rn(v.x, v.y));
    u.y = h22u(__floats2half2_rn(v.z, v.w));
    reinterpret_cast<uint2*>(g_half + (size_t)r * (PC / 2))[c4] = u;
}

// ---------------- Kernel 2: rectify (R10 geometry + HFMA2 accumulation) ----------------
// 96 threads per CTA, one point per CTA; thread t owns channels [4t, 4t+4).
// Gathers: 16 x LDG.64 of fp16 per thread, accumulated with HFMA2 (2 banks).
// Blocks [0, NPTS): compute. Blocks [NPTS, NPTS+PB): cls-token copy.
__global__ void __launch_bounds__(96, 17)
k_rectify_kernel(const float* __restrict__ f,
                 const float* __restrict__ dist,
                 const float* __restrict__ rf,
                 const float* __restrict__ knw,
                 const int* __restrict__ idx,
                 float* __restrict__ out)
{
    const int p   = blockIdx.x;
    const int tid = threadIdx.x;

    if (p >= NPTS) {
        const int b = p - NPTS;
        const float4* src = reinterpret_cast<const float4*>(f  + (size_t)b * PNTOT * PC);
        float4*       dst = reinterpret_cast<float4*>(out + (size_t)b * PNTOT * PC);
        dst[tid] = src[tid];
        return;
    }

    const int b = p >> 7;
    const int n = p & (PN - 1);

    __shared__ unsigned swh[PGS];   // half2-packed normalized weights
    __shared__ int      soff[PGS];  // gather row byte offsets into g_half
    __shared__ float    sred[3];    // per-warp RMS partials

    if (tid < PGS) {
        const float d = dist[p * PGS + tid];
        float wv = 1.0f / (d + EPSW);
        float s  = wv;
        #pragma unroll
        for (int o = 8; o > 0; o >>= 1)
            s += __shfl_xor_sync(0x0000FFFFu, s, o, 16);
        swh[tid]  = h22u(__float2half2_rn(wv / s));
        soff[tid] = idx[p * PGS + tid] * (PC * 2);   // row stride 768 bytes
    }
    __syncthreads();

    // x row (fp32, exact)
    const int xoff = (b * PNTOT + 1 + n) * PC;
    const float4 x4 = reinterpret_cast<const float4*>(f + (size_t)xoff)[tid];

    // Weighted gather: 16 x LDG.64, HFMA2 accumulation in two banks (even/odd g)
    const char* hb = reinterpret_cast<const char*>(g_half) + tid * 8;
    __half2 A0 = u2h2(0), A1 = u2h2(0);
    __half2 B0 = u2h2(0), B1 = u2h2(0);

    #pragma unroll
    for (int g = 0; g < PGS; g += 2) {
        const uint2 v0 = *reinterpret_cast<const uint2*>(hb + soff[g]);
        const __half2 w0 = u2h2(swh[g]);
        A0 = __hfma2(w0, u2h2(v0.x), A0);
        A1 = __hfma2(w0, u2h2(v0.y), A1);

        const uint2 v1 = *reinterpret_cast<const uint2*>(hb + soff[g + 1]);
        const __half2 w1 = u2h2(swh[g + 1]);
        B0 = __hfma2(w1, u2h2(v1.x), B0);
        B1 = __hfma2(w1, u2h2(v1.y), B1);
    }

    // Combine banks in fp32; sf = sum(w*nb) - x  (weights sum to 1)
    const float2 a0 = __half22float2(A0), b0f = __half22float2(B0);
    const float2 a1 = __half22float2(A1), b1f = __half22float2(B1);

    const float s0 = a0.x + b0f.x - x4.x;
    const float s1 = a0.y + b0f.y - x4.y;
    const float s2 = a1.x + b1f.x - x4.z;
    const float s3 = a1.y + b1f.y - x4.w;

    // RMS over the 384-channel row
    float ss = s0 * s0 + s1 * s1 + s2 * s2 + s3 * s3;
    #pragma unroll
    for (int o = 16; o > 0; o >>= 1)
        ss += __shfl_xor_sync(0xFFFFFFFFu, ss, o);
    if ((tid & 31) == 0) sred[tid >> 5] = ss;
    __syncthreads();
    const float tot = sred[0] + sred[1] + sred[2];
    const float inv = rsqrtf(tot * (1.0f / PC) + RMSE);

    // out = rf[1+n] + x + (sf * inv) * knorm_w
    const float4 r4 = reinterpret_cast<const float4*>(rf + (size_t)(1 + n) * PC)[tid];
    const float4 k4 = reinterpret_cast<const float4*>(knw)[tid];

    float4 o4;
    o4.x = r4.x + x4.x + s0 * inv * k4.x;
    o4.y = r4.y + x4.y + s1 * inv * k4.y;
    o4.z = r4.z + x4.z + s2 * inv * k4.z;
    o4.w = r4.w + x4.w + s3 * inv * k4.w;
    reinterpret_cast<float4*>(out + (size_t)xoff)[tid] = o4;
}

extern "C" void kernel_launch(void* const* d_in, const int* in_sizes, int n_in,
                              void* d_out, int out_size)
{
    const float* f    = (const float*)d_in[0];
    const float* dist = (const float*)d_in[1];
    const float* rf   = (const float*)d_in[2];
    const float* knw  = (const float*)d_in[3];
    const int*   idx  = (const int*)d_in[4];
    float*       out  = (float*)d_out;

    const int conv_threads = NPTS * (PC / 4);              // 1,572,864
    k_convert_kernel<<<conv_threads / 256, 256>>>(f);

    const int grid = NPTS + PB;                            // 16384 compute + 128 cls
    k_rectify_kernel<<<grid, 96>>>(f, dist, rf, knw, idx, out);
}

// round 16
// speedup vs baseline: 1.0850x; 1.0047x over previous
#include <cuda_runtime.h>
#include <cuda_fp16.h>
#include <cstdint>

// Problem constants (K_Rectify): B=128, NTOT=129, N=128, GS=16, C=384
#define PB    128
#define PNTOT 129
#define PN    128
#define PGS   16
#define PC    384
#define EPSW  0.05f
#define RMSE  1e-6f

#define NPTS (PB * PN)   // 16384

// fp16 staging of the gatherable point rows f[:,1:,:], row j = idx value.
// 16384 rows x 384 halves = 12.58 MB static __device__ scratch.
__device__ __align__(16) __half2 g_half[(size_t)NPTS * (PC / 2)];

static __device__ __forceinline__ __half2 u2h2(unsigned u) {
    __half2 h; *reinterpret_cast<unsigned*>(&h) = u; return h;
}
static __device__ __forceinline__ unsigned h22u(__half2 h) {
    return *reinterpret_cast<unsigned*>(&h);
}

// ---------------- Kernel 1: fp32 -> fp16 staging ----------------
__global__ void __launch_bounds__(256)
k_convert_kernel(const float* __restrict__ f)
{
    const int t  = blockIdx.x * blockDim.x + threadIdx.x;   // float4 slot
    const int r  = t / (PC / 4);                            // point row 0..16383
    const int c4 = t - r * (PC / 4);                        // float4 column 0..95

    const float4 v = reinterpret_cast<const float4*>(
        f + (size_t)((r >> 7) * PNTOT + 1 + (r & (PN - 1))) * PC)[c4];

    uint2 u;
    u.x = h22u(__floats2half2_rn(v.x, v.y));
    u.y = h22u(__floats2half2_rn(v.z, v.w));
    reinterpret_cast<uint2*>(g_half + (size_t)r * (PC / 2))[c4] = u;
}

// ---------------- Kernel 2: rectify ----------------
// 96 threads per CTA, one point per CTA; thread t owns channels [4t, 4t+4).
// All 16 gather LDG.64s issued as one batch (MLP=16/thread), then HFMA2
// accumulation in two banks. launch_bounds(96,12) gives ptxas reg headroom
// (cap 56) to keep the whole batch in flight.
__global__ void __launch_bounds__(96, 12)
k_rectify_kernel(const float* __restrict__ f,
                 const float* __restrict__ dist,
                 const float* __restrict__ rf,
                 const float* __restrict__ knw,
                 const int* __restrict__ idx,
                 float* __restrict__ out)
{
    const int p   = blockIdx.x;
    const int tid = threadIdx.x;

    if (p >= NPTS) {
        const int b = p - NPTS;
        const float4* src = reinterpret_cast<const float4*>(f  + (size_t)b * PNTOT * PC);
        float4*       dst = reinterpret_cast<float4*>(out + (size_t)b * PNTOT * PC);
        dst[tid] = src[tid];
        return;
    }

    const int b = p >> 7;
    const int n = p & (PN - 1);

    __shared__ unsigned swh[PGS];   // half2-packed normalized weights
    __shared__ int      soff[PGS];  // gather row byte offsets into g_half
    __shared__ float    sred[3];    // per-warp RMS partials

    if (tid < PGS) {
        const float d = dist[p * PGS + tid];
        float wv = 1.0f / (d + EPSW);
        float s  = wv;
        #pragma unroll
        for (int o = 8; o > 0; o >>= 1)
            s += __shfl_xor_sync(0x0000FFFFu, s, o, 16);
        swh[tid]  = h22u(__float2half2_rn(wv / s));
        soff[tid] = idx[p * PGS + tid] * (PC * 2);   // row stride 768 bytes
    }
    __syncthreads();

    // Batch ALL 16 gather loads first — maximum memory-level parallelism.
    const char* hb = reinterpret_cast<const char*>(g_half) + tid * 8;
    uint2 v[PGS];
    #pragma unroll
    for (int g = 0; g < PGS; g++)
        v[g] = *reinterpret_cast<const uint2*>(hb + soff[g]);

    // x row (fp32, exact) — issued after the gather burst, independent.
    const int xoff = (b * PNTOT + 1 + n) * PC;
    const float4 x4 = reinterpret_cast<const float4*>(f + (size_t)xoff)[tid];

    // HFMA2 accumulation in two banks (even/odd g) — same numeric path as R15.
    __half2 A0 = u2h2(0), A1 = u2h2(0);
    __half2 B0 = u2h2(0), B1 = u2h2(0);
    #pragma unroll
    for (int g = 0; g < PGS; g += 2) {
        const __half2 w0 = u2h2(swh[g]);
        A0 = __hfma2(w0, u2h2(v[g].x), A0);
        A1 = __hfma2(w0, u2h2(v[g].y), A1);
        const __half2 w1 = u2h2(swh[g + 1]);
        B0 = __hfma2(w1, u2h2(v[g + 1].x), B0);
        B1 = __hfma2(w1, u2h2(v[g + 1].y), B1);
    }

    // Combine banks in fp32; sf = sum(w*nb) - x  (weights sum to 1)
    const float2 a0 = __half22float2(A0), b0f = __half22float2(B0);
    const float2 a1 = __half22float2(A1), b1f = __half22float2(B1);

    const float s0 = a0.x + b0f.x - x4.x;
    const float s1 = a0.y + b0f.y - x4.y;
    const float s2 = a1.x + b1f.x - x4.z;
    const float s3 = a1.y + b1f.y - x4.w;

    // RMS over the 384-channel row
    float ss = s0 * s0 + s1 * s1 + s2 * s2 + s3 * s3;
    #pragma unroll
    for (int o = 16; o > 0; o >>= 1)
        ss += __shfl_xor_sync(0xFFFFFFFFu, ss, o);
    if ((tid & 31) == 0) sred[tid >> 5] = ss;
    __syncthreads();
    const float tot = sred[0] + sred[1] + sred[2];
    const float inv = rsqrtf(tot * (1.0f / PC) + RMSE);

    // out = rf[1+n] + x + (sf * inv) * knorm_w
    const float4 r4 = reinterpret_cast<const float4*>(rf + (size_t)(1 + n) * PC)[tid];
    const float4 k4 = reinterpret_cast<const float4*>(knw)[tid];

    float4 o4;
    o4.x = r4.x + x4.x + s0 * inv * k4.x;
    o4.y = r4.y + x4.y + s1 * inv * k4.y;
    o4.z = r4.z + x4.z + s2 * inv * k4.z;
    o4.w = r4.w + x4.w + s3 * inv * k4.w;
    reinterpret_cast<float4*>(out + (size_t)xoff)[tid] = o4;
}

extern "C" void kernel_launch(void* const* d_in, const int* in_sizes, int n_in,
                              void* d_out, int out_size)
{
    const float* f    = (const float*)d_in[0];
    const float* dist = (const float*)d_in[1];
    const float* rf   = (const float*)d_in[2];
    const float* knw  = (const float*)d_in[3];
    const int*   idx  = (const int*)d_in[4];
    float*       out  = (float*)d_out;

    const int conv_threads = NPTS * (PC / 4);              // 1,572,864
    k_convert_kernel<<<conv_threads / 256, 256>>>(f);

    const int grid = NPTS + PB;                            // 16384 compute + 128 cls
    k_rectify_kernel<<<grid, 96>>>(f, dist, rf, knw, idx, out);
}